// round 2
// baseline (speedup 1.0000x reference)
#include <cuda_runtime.h>
#include <cstdint>

#define N_NODES 50000
#define IN_CH   256
#define HID_CH  64
#define N_EDGES 800000

// Scratch for xw = x @ W  (50000 x 64 fp32 = 12.8 MB, L2-resident)
__device__ float g_xw[N_NODES * HID_CH];

// ---------------------------------------------------------------------------
// GEMM: g_xw = x @ W.  Block = 512 threads, tile 128 rows x 64 cols.
// Thread tile 4x4. W (256x64) + x k-tile (128x64) live in dynamic smem,
// both padded to row stride 68 floats for conflict-free float4 access.
// ---------------------------------------------------------------------------
#define GEMM_ROWS    128
#define SMEM_STRIDE  68
#define GEMM_SMEM_BYTES ((IN_CH * SMEM_STRIDE + GEMM_ROWS * SMEM_STRIDE) * 4)

__global__ __launch_bounds__(512, 1)
void gemm_kernel(const float* __restrict__ x, const float* __restrict__ W) {
    extern __shared__ float smem[];
    float* Ws = smem;                         // [256][68]
    float* xs = smem + IN_CH * SMEM_STRIDE;   // [128][68]

    const int tid  = threadIdx.x;
    const int row0 = blockIdx.x * GEMM_ROWS;
    const int tc   = tid & 15;   // 16 col-groups of 4 cols
    const int tr   = tid >> 4;   // 32 row-groups of 4 rows

    // Load full W into smem (one time): 16384 elements / 512 threads = 32 each
    for (int i = tid; i < IN_CH * HID_CH; i += 512) {
        int k = i >> 6, c = i & 63;
        Ws[k * SMEM_STRIDE + c] = W[i];
    }

    float acc[4][4] = {};

    for (int k0 = 0; k0 < IN_CH; k0 += 64) {
        __syncthreads();
        // Load x tile: 128 rows x 64 k. 4 threads per row, 4 float4 each.
        {
            int r  = tid >> 2;
            int ch = tid & 3;
            int grow = row0 + r;
            if (grow >= N_NODES) grow = N_NODES - 1;  // clamp; guarded at store
            const float4* srcp = (const float4*)(x + (size_t)grow * IN_CH + k0);
            float4* dstp = (float4*)(xs + r * SMEM_STRIDE);
            #pragma unroll
            for (int j = 0; j < 4; j++) dstp[ch * 4 + j] = srcp[ch * 4 + j];
        }
        __syncthreads();

        #pragma unroll
        for (int k = 0; k < 64; k += 4) {
            float4 xv[4], wv[4];
            #pragma unroll
            for (int rr = 0; rr < 4; rr++)
                xv[rr] = *(const float4*)(xs + (tr * 4 + rr) * SMEM_STRIDE + k);
            #pragma unroll
            for (int kk = 0; kk < 4; kk++)
                wv[kk] = *(const float4*)(Ws + (k0 + k + kk) * SMEM_STRIDE + tc * 4);

            #pragma unroll
            for (int kk = 0; kk < 4; kk++) {
                float w0 = wv[kk].x, w1 = wv[kk].y, w2 = wv[kk].z, w3 = wv[kk].w;
                #pragma unroll
                for (int rr = 0; rr < 4; rr++) {
                    float xr = (kk == 0) ? xv[rr].x : (kk == 1) ? xv[rr].y
                             : (kk == 2) ? xv[rr].z : xv[rr].w;
                    acc[rr][0] = fmaf(xr, w0, acc[rr][0]);
                    acc[rr][1] = fmaf(xr, w1, acc[rr][1]);
                    acc[rr][2] = fmaf(xr, w2, acc[rr][2]);
                    acc[rr][3] = fmaf(xr, w3, acc[rr][3]);
                }
            }
        }
    }

    #pragma unroll
    for (int rr = 0; rr < 4; rr++) {
        int grow = row0 + tr * 4 + rr;
        if (grow < N_NODES) {
            float4 v = make_float4(acc[rr][0], acc[rr][1], acc[rr][2], acc[rr][3]);
            *(float4*)(g_xw + (size_t)grow * HID_CH + tc * 4) = v;
        }
    }
}

// ---------------------------------------------------------------------------
// Init: out[n][c] = bias[c]  (so the scatter can accumulate straight into out)
// ---------------------------------------------------------------------------
__global__ void init_kernel(float* __restrict__ out, const float* __restrict__ bias) {
    int i = blockIdx.x * blockDim.x + threadIdx.x;   // float4 index
    if (i >= N_NODES * HID_CH / 4) return;
    ((float4*)out)[i] = ((const float4*)bias)[i & 15];
}

// ---------------------------------------------------------------------------
// Scatter: out[dst] += g_xw[src] for each edge. edge_index is int32 [2, E]
// (JAX without x64 downgrades int64 -> int32). 4 threads per edge, each
// handles 16 channels via 4x red.global.add.v4.f32 (L2-side vector reduce).
// ---------------------------------------------------------------------------
__global__ void scatter_kernel(const int* __restrict__ ei,
                               float* __restrict__ out) {
    int idx  = blockIdx.x * blockDim.x + threadIdx.x;
    int edge = idx >> 2;
    if (edge >= N_EDGES) return;
    int part = idx & 3;

    int src = ei[edge];
    int dst = ei[N_EDGES + edge];
    // Defensive: if dtype assumption is wrong, skip rather than fault.
    if ((unsigned)src >= N_NODES || (unsigned)dst >= N_NODES) return;

    const float4* s = (const float4*)(g_xw + (size_t)src * HID_CH + part * 16);
    float*        d = out + (size_t)dst * HID_CH + part * 16;

    #pragma unroll
    for (int j = 0; j < 4; j++) {
        float4 v = s[j];
        asm volatile("red.global.add.v4.f32 [%0], {%1, %2, %3, %4};"
                     :: "l"(d + j * 4), "f"(v.x), "f"(v.y), "f"(v.z), "f"(v.w)
                     : "memory");
    }
}

// ---------------------------------------------------------------------------
// PReLU in place: out = out > 0 ? out : a[c] * out
// ---------------------------------------------------------------------------
__global__ void prelu_kernel(float* __restrict__ out, const float* __restrict__ a) {
    int i = blockIdx.x * blockDim.x + threadIdx.x;   // float4 index
    if (i >= N_NODES * HID_CH / 4) return;
    float4 v  = ((float4*)out)[i];
    float4 av = ((const float4*)a)[i & 15];
    v.x = v.x > 0.f ? v.x : av.x * v.x;
    v.y = v.y > 0.f ? v.y : av.y * v.y;
    v.z = v.z > 0.f ? v.z : av.z * v.z;
    v.w = v.w > 0.f ? v.w : av.w * v.w;
    ((float4*)out)[i] = v;
}

// ---------------------------------------------------------------------------
extern "C" void kernel_launch(void* const* d_in, const int* in_sizes, int n_in,
                              void* d_out, int out_size) {
    const float* x     = (const float*)d_in[0];
    const int*   ei    = (const int*)d_in[1];
    const float* W     = (const float*)d_in[2];
    const float* bias  = (const float*)d_in[3];
    const float* prelu = (const float*)d_in[4];
    float*       out   = (float*)d_out;

    cudaFuncSetAttribute(gemm_kernel, cudaFuncAttributeMaxDynamicSharedMemorySize,
                         GEMM_SMEM_BYTES);

    int gemm_blocks = (N_NODES + GEMM_ROWS - 1) / GEMM_ROWS;        // 391
    gemm_kernel<<<gemm_blocks, 512, GEMM_SMEM_BYTES>>>(x, W);

    int vec_elems = N_NODES * HID_CH / 4;                            // 800000
    init_kernel<<<(vec_elems + 255) / 256, 256>>>(out, bias);

    int scat_threads = N_EDGES * 4;                                  // 3.2M
    scatter_kernel<<<(scat_threads + 255) / 256, 256>>>(ei, out);

    prelu_kernel<<<(vec_elems + 255) / 256, 256>>>(out, prelu);
}

// round 3
// speedup vs baseline: 1.2345x; 1.2345x over previous
#include <cuda_runtime.h>
#include <cstdint>

#define N_NODES 50000
#define IN_CH   256
#define HID_CH  64
#define N_EDGES 800000
#define NBINS   N_NODES
#define SCAN_BLOCKS 196   // 196*256 = 50176 >= 50000

// Scratch (device globals; no allocation allowed)
__device__ float g_xw[N_NODES * HID_CH];      // x @ W
__device__ int   g_cnt[NBINS];                // per-dst degree
__device__ int   g_off[NBINS + 1];            // CSR offsets (exclusive scan)
__device__ int   g_cursor[NBINS];             // running write cursor
__device__ int   g_bsum[SCAN_BLOCKS];         // per-block scan sums
__device__ int   g_bsum2[SCAN_BLOCKS];        // scanned block sums
__device__ int   g_sorted_src[N_EDGES];       // src ids grouped by dst

// ---------------------------------------------------------------------------
// GEMM: g_xw = x @ W. (unchanged from R2 — known correct, ~FMA-pipe bound)
// ---------------------------------------------------------------------------
#define GEMM_ROWS    128
#define SMEM_STRIDE  68
#define GEMM_SMEM_BYTES ((IN_CH * SMEM_STRIDE + GEMM_ROWS * SMEM_STRIDE) * 4)

__global__ __launch_bounds__(512, 1)
void gemm_kernel(const float* __restrict__ x, const float* __restrict__ W) {
    extern __shared__ float smem[];
    float* Ws = smem;                         // [256][68]
    float* xs = smem + IN_CH * SMEM_STRIDE;   // [128][68]

    const int tid  = threadIdx.x;
    const int row0 = blockIdx.x * GEMM_ROWS;
    const int tc   = tid & 15;
    const int tr   = tid >> 4;

    for (int i = tid; i < IN_CH * HID_CH; i += 512) {
        int k = i >> 6, c = i & 63;
        Ws[k * SMEM_STRIDE + c] = W[i];
    }

    float acc[4][4] = {};

    for (int k0 = 0; k0 < IN_CH; k0 += 64) {
        __syncthreads();
        {
            int r  = tid >> 2;
            int ch = tid & 3;
            int grow = row0 + r;
            if (grow >= N_NODES) grow = N_NODES - 1;
            const float4* srcp = (const float4*)(x + (size_t)grow * IN_CH + k0);
            float4* dstp = (float4*)(xs + r * SMEM_STRIDE);
            #pragma unroll
            for (int j = 0; j < 4; j++) dstp[ch * 4 + j] = srcp[ch * 4 + j];
        }
        __syncthreads();

        #pragma unroll
        for (int k = 0; k < 64; k += 4) {
            float4 xv[4], wv[4];
            #pragma unroll
            for (int rr = 0; rr < 4; rr++)
                xv[rr] = *(const float4*)(xs + (tr * 4 + rr) * SMEM_STRIDE + k);
            #pragma unroll
            for (int kk = 0; kk < 4; kk++)
                wv[kk] = *(const float4*)(Ws + (k0 + k + kk) * SMEM_STRIDE + tc * 4);

            #pragma unroll
            for (int kk = 0; kk < 4; kk++) {
                float w0 = wv[kk].x, w1 = wv[kk].y, w2 = wv[kk].z, w3 = wv[kk].w;
                #pragma unroll
                for (int rr = 0; rr < 4; rr++) {
                    float xr = (kk == 0) ? xv[rr].x : (kk == 1) ? xv[rr].y
                             : (kk == 2) ? xv[rr].z : xv[rr].w;
                    acc[rr][0] = fmaf(xr, w0, acc[rr][0]);
                    acc[rr][1] = fmaf(xr, w1, acc[rr][1]);
                    acc[rr][2] = fmaf(xr, w2, acc[rr][2]);
                    acc[rr][3] = fmaf(xr, w3, acc[rr][3]);
                }
            }
        }
    }

    #pragma unroll
    for (int rr = 0; rr < 4; rr++) {
        int grow = row0 + tr * 4 + rr;
        if (grow < N_NODES) {
            float4 v = make_float4(acc[rr][0], acc[rr][1], acc[rr][2], acc[rr][3]);
            *(float4*)(g_xw + (size_t)grow * HID_CH + tc * 4) = v;
        }
    }
}

// ---------------------------------------------------------------------------
// CSR build: histogram -> scan -> reorder
// ---------------------------------------------------------------------------
__global__ void zero_kernel() {
    int i = blockIdx.x * blockDim.x + threadIdx.x;
    if (i < NBINS) g_cnt[i] = 0;
}

__global__ void hist_kernel(const int* __restrict__ ei) {
    int e = blockIdx.x * blockDim.x + threadIdx.x;
    if (e >= N_EDGES) return;
    int dst = ei[N_EDGES + e];
    if ((unsigned)dst < NBINS) atomicAdd(&g_cnt[dst], 1);
}

__global__ void scan_a_kernel() {
    __shared__ int s[256];
    int t = threadIdx.x, i = blockIdx.x * 256 + t;
    int v = (i < NBINS) ? g_cnt[i] : 0;
    s[t] = v;
    __syncthreads();
    #pragma unroll
    for (int d = 1; d < 256; d <<= 1) {
        int add = (t >= d) ? s[t - d] : 0;
        __syncthreads();
        s[t] += add;
        __syncthreads();
    }
    if (i < NBINS) g_off[i] = s[t] - v;             // local exclusive
    if (t == 255) g_bsum[blockIdx.x] = s[255];      // block total
}

__global__ void scan_b_kernel() {
    __shared__ int s[256];
    int t = threadIdx.x;
    int v = (t < SCAN_BLOCKS) ? g_bsum[t] : 0;
    s[t] = v;
    __syncthreads();
    #pragma unroll
    for (int d = 1; d < 256; d <<= 1) {
        int add = (t >= d) ? s[t - d] : 0;
        __syncthreads();
        s[t] += add;
        __syncthreads();
    }
    if (t < SCAN_BLOCKS) g_bsum2[t] = s[t] - v;     // exclusive
}

__global__ void scan_c_kernel() {
    int i = blockIdx.x * blockDim.x + threadIdx.x;
    if (i < NBINS) {
        int off = g_off[i] + g_bsum2[blockIdx.x * 256 / 256 == 0 ? 0 : 0];  // placeholder
        off = g_off[i] + g_bsum2[i >> 8];
        g_off[i]    = off;
        g_cursor[i] = off;
    }
    if (i == 0) g_off[NBINS] = N_EDGES;
}

__global__ void reorder_kernel(const int* __restrict__ ei) {
    int e = blockIdx.x * blockDim.x + threadIdx.x;
    if (e >= N_EDGES) return;
    int src = ei[e];
    int dst = ei[N_EDGES + e];
    if ((unsigned)src >= N_NODES || (unsigned)dst >= N_NODES) return;
    int pos = atomicAdd(&g_cursor[dst], 1);
    g_sorted_src[pos] = src;
}

// ---------------------------------------------------------------------------
// Gather-sum + fused bias + PReLU. One warp per dst node.
// Lane layout: slot = lane>>4 (2 edge slots), cg = lane&15 (4 channels each).
// ---------------------------------------------------------------------------
__global__ __launch_bounds__(256)
void gather_kernel(const float* __restrict__ bias,
                   const float* __restrict__ prelu_a,
                   float* __restrict__ out) {
    int warp = (blockIdx.x * blockDim.x + threadIdx.x) >> 5;
    int lane = threadIdx.x & 31;
    if (warp >= N_NODES) return;

    int beg = g_off[warp];
    int end = g_off[warp + 1];
    int slot = lane >> 4;
    int cg   = lane & 15;

    float4 acc = make_float4(0.f, 0.f, 0.f, 0.f);
    for (int i = beg + slot; i < end; i += 2) {
        int src = g_sorted_src[i];
        float4 v = *(const float4*)(g_xw + (size_t)src * HID_CH + cg * 4);
        acc.x += v.x; acc.y += v.y; acc.z += v.z; acc.w += v.w;
    }

    // cross-slot reduction (slot 0 <- slot 1)
    acc.x += __shfl_xor_sync(0xFFFFFFFFu, acc.x, 16);
    acc.y += __shfl_xor_sync(0xFFFFFFFFu, acc.y, 16);
    acc.z += __shfl_xor_sync(0xFFFFFFFFu, acc.z, 16);
    acc.w += __shfl_xor_sync(0xFFFFFFFFu, acc.w, 16);

    if (slot == 0) {
        float4 b = ((const float4*)bias)[cg];
        float4 a = ((const float4*)prelu_a)[cg];
        float4 r;
        r.x = acc.x + b.x; r.x = r.x > 0.f ? r.x : a.x * r.x;
        r.y = acc.y + b.y; r.y = r.y > 0.f ? r.y : a.y * r.y;
        r.z = acc.z + b.z; r.z = r.z > 0.f ? r.z : a.z * r.z;
        r.w = acc.w + b.w; r.w = r.w > 0.f ? r.w : a.w * r.w;
        ((float4*)(out + (size_t)warp * HID_CH))[cg] = r;
    }
}

// ---------------------------------------------------------------------------
extern "C" void kernel_launch(void* const* d_in, const int* in_sizes, int n_in,
                              void* d_out, int out_size) {
    const float* x     = (const float*)d_in[0];
    const int*   ei    = (const int*)d_in[1];
    const float* W     = (const float*)d_in[2];
    const float* bias  = (const float*)d_in[3];
    const float* prelu = (const float*)d_in[4];
    float*       out   = (float*)d_out;

    cudaFuncSetAttribute(gemm_kernel, cudaFuncAttributeMaxDynamicSharedMemorySize,
                         GEMM_SMEM_BYTES);

    int gemm_blocks = (N_NODES + GEMM_ROWS - 1) / GEMM_ROWS;
    gemm_kernel<<<gemm_blocks, 512, GEMM_SMEM_BYTES>>>(x, W);

    zero_kernel<<<(NBINS + 255) / 256, 256>>>();
    hist_kernel<<<(N_EDGES + 255) / 256, 256>>>(ei);
    scan_a_kernel<<<SCAN_BLOCKS, 256>>>();
    scan_b_kernel<<<1, 256>>>();
    scan_c_kernel<<<SCAN_BLOCKS, 256>>>();
    reorder_kernel<<<(N_EDGES + 255) / 256, 256>>>(ei);

    int gather_blocks = (N_NODES * 32 + 255) / 256;   // 1 warp per node
    gather_kernel<<<gather_blocks, 256>>>(bias, prelu, out);
}

// round 4
// speedup vs baseline: 1.8416x; 1.4918x over previous
#include <cuda_runtime.h>
#include <cuda_bf16.h>
#include <cstdint>

#define N_NODES 50000
#define IN_CH   256
#define HID_CH  64
#define N_EDGES 800000
#define NBINS   N_NODES
#define SCAN_BLOCKS 196   // 196*256 = 50176 >= 50000

#define WT_STRIDE 264     // padded k-stride (bf16 elems) for W^T: conflict-free LDS

// Scratch (device globals; no allocation allowed)
__device__ float g_xw[N_NODES * HID_CH];                       // x @ W
__device__ __align__(16) __nv_bfloat16 g_WhiT[HID_CH * WT_STRIDE];
__device__ __align__(16) __nv_bfloat16 g_WloT[HID_CH * WT_STRIDE];
__device__ int   g_cnt[NBINS];
__device__ int   g_off[NBINS + 1];
__device__ int   g_cursor[NBINS];
__device__ int   g_bsum[SCAN_BLOCKS];
__device__ int   g_bsum2[SCAN_BLOCKS];
__device__ int   g_sorted_src[N_EDGES];

// ---------------------------------------------------------------------------
// W split: W[k][n] fp32 -> transposed bf16 hi/lo tables W^T[n][k] (padded).
// hi = bf16(w), lo = bf16(w - float(hi));  w ≈ hi + lo to ~2^-17.
// ---------------------------------------------------------------------------
__global__ void convert_w_kernel(const float* __restrict__ W) {
    int i = blockIdx.x * blockDim.x + threadIdx.x;
    if (i >= IN_CH * HID_CH) return;
    int k = i >> 6, n = i & 63;
    float w = W[i];
    __nv_bfloat16 hi = __float2bfloat16_rn(w);
    float rem = w - __bfloat162float(hi);
    g_WhiT[n * WT_STRIDE + k] = hi;
    g_WloT[n * WT_STRIDE + k] = __float2bfloat16_rn(rem);
}

// ---------------------------------------------------------------------------
// Tensor-core GEMM: g_xw = x @ W via bf16-split mma.sync (3 passes).
// Block: 256 thr (8 warps), 128 rows/block. Warp tile: 16 rows x 64 cols.
// ---------------------------------------------------------------------------
#define GEMM_SMEM_BYTES (2 * HID_CH * WT_STRIDE * 2)   // hi + lo tables

__device__ __forceinline__ void mma16816(float d[4], const uint32_t a[4],
                                         uint32_t b0, uint32_t b1) {
    asm volatile(
        "mma.sync.aligned.m16n8k16.row.col.f32.bf16.bf16.f32 "
        "{%0,%1,%2,%3}, {%4,%5,%6,%7}, {%8,%9}, {%0,%1,%2,%3};\n"
        : "+f"(d[0]), "+f"(d[1]), "+f"(d[2]), "+f"(d[3])
        : "r"(a[0]), "r"(a[1]), "r"(a[2]), "r"(a[3]), "r"(b0), "r"(b1));
}

__global__ __launch_bounds__(256, 3)
void gemm_mma_kernel(const float* __restrict__ x) {
    extern __shared__ __align__(16) __nv_bfloat16 sW[];
    __nv_bfloat16* sWhi = sW;
    __nv_bfloat16* sWlo = sW + HID_CH * WT_STRIDE;

    const int tid = threadIdx.x;
    // Stage both W tables into smem (uint4 copies)
    {
        const uint4* shi = (const uint4*)g_WhiT;
        const uint4* slo = (const uint4*)g_WloT;
        uint4* dhi = (uint4*)sWhi;
        uint4* dlo = (uint4*)sWlo;
        const int n16 = HID_CH * WT_STRIDE * 2 / 16;   // 2112
        for (int i = tid; i < n16; i += 256) { dhi[i] = shi[i]; dlo[i] = slo[i]; }
    }
    __syncthreads();

    const int lane = tid & 31;
    const int warp = tid >> 5;
    const int row0 = blockIdx.x * 128 + warp * 16;
    const int rA   = lane >> 2;        // 0..7
    const int cA   = (lane & 3) * 2;   // 0,2,4,6

    int r0 = row0 + rA;     if (r0 > N_NODES - 1) r0 = N_NODES - 1;
    int r1 = row0 + rA + 8; if (r1 > N_NODES - 1) r1 = N_NODES - 1;
    const float* xr0 = x + (size_t)r0 * IN_CH;
    const float* xr1 = x + (size_t)r1 * IN_CH;

    float d[8][4];
    #pragma unroll
    for (int nt = 0; nt < 8; nt++)
        #pragma unroll
        for (int j = 0; j < 4; j++) d[nt][j] = 0.f;

    #pragma unroll 4
    for (int k0 = 0; k0 < IN_CH; k0 += 16) {
        // A fragments: rows (r0, r1), k chunks (k0+cA, k0+8+cA)
        float2 f00 = *(const float2*)(xr0 + k0 + cA);
        float2 f10 = *(const float2*)(xr1 + k0 + cA);
        float2 f01 = *(const float2*)(xr0 + k0 + 8 + cA);
        float2 f11 = *(const float2*)(xr1 + k0 + 8 + cA);

        __nv_bfloat162 h00 = __floats2bfloat162_rn(f00.x, f00.y);
        __nv_bfloat162 h10 = __floats2bfloat162_rn(f10.x, f10.y);
        __nv_bfloat162 h01 = __floats2bfloat162_rn(f01.x, f01.y);
        __nv_bfloat162 h11 = __floats2bfloat162_rn(f11.x, f11.y);

        __nv_bfloat162 l00 = __floats2bfloat162_rn(f00.x - __low2float(h00),
                                                   f00.y - __high2float(h00));
        __nv_bfloat162 l10 = __floats2bfloat162_rn(f10.x - __low2float(h10),
                                                   f10.y - __high2float(h10));
        __nv_bfloat162 l01 = __floats2bfloat162_rn(f01.x - __low2float(h01),
                                                   f01.y - __high2float(h01));
        __nv_bfloat162 l11 = __floats2bfloat162_rn(f11.x - __low2float(h11),
                                                   f11.y - __high2float(h11));

        uint32_t ahi[4] = { *(uint32_t*)&h00, *(uint32_t*)&h10,
                            *(uint32_t*)&h01, *(uint32_t*)&h11 };
        uint32_t alo[4] = { *(uint32_t*)&l00, *(uint32_t*)&l10,
                            *(uint32_t*)&l01, *(uint32_t*)&l11 };

        const int nB = lane >> 2;          // n within 8-wide tile
        const int kB = (lane & 3) * 2;     // k pair within chunk

        #pragma unroll
        for (int nt = 0; nt < 8; nt++) {
            int base = (nt * 8 + nB) * WT_STRIDE + k0 + kB;
            uint32_t bh0 = *(const uint32_t*)(sWhi + base);
            uint32_t bh1 = *(const uint32_t*)(sWhi + base + 8);
            uint32_t bl0 = *(const uint32_t*)(sWlo + base);
            uint32_t bl1 = *(const uint32_t*)(sWlo + base + 8);
            mma16816(d[nt], ahi, bh0, bh1);   // x_hi * W_hi
            mma16816(d[nt], ahi, bl0, bl1);   // x_hi * W_lo
            mma16816(d[nt], alo, bh0, bh1);   // x_lo * W_hi
        }
    }

    // Store D fragments: rows row0+rA, row0+rA+8; cols nt*8 + cA
    int rr0 = row0 + rA;
    int rr1 = rr0 + 8;
    #pragma unroll
    for (int nt = 0; nt < 8; nt++) {
        int col = nt * 8 + cA;
        if (rr0 < N_NODES)
            *(float2*)(g_xw + (size_t)rr0 * HID_CH + col) = make_float2(d[nt][0], d[nt][1]);
        if (rr1 < N_NODES)
            *(float2*)(g_xw + (size_t)rr1 * HID_CH + col) = make_float2(d[nt][2], d[nt][3]);
    }
}

// ---------------------------------------------------------------------------
// CSR build: histogram -> scan -> reorder (unchanged from R3, passing)
// ---------------------------------------------------------------------------
__global__ void zero_kernel() {
    int i = blockIdx.x * blockDim.x + threadIdx.x;
    if (i < NBINS) g_cnt[i] = 0;
}

__global__ void hist_kernel(const int* __restrict__ ei) {
    int e = blockIdx.x * blockDim.x + threadIdx.x;
    if (e >= N_EDGES) return;
    int dst = ei[N_EDGES + e];
    if ((unsigned)dst < NBINS) atomicAdd(&g_cnt[dst], 1);
}

__global__ void scan_a_kernel() {
    __shared__ int s[256];
    int t = threadIdx.x, i = blockIdx.x * 256 + t;
    int v = (i < NBINS) ? g_cnt[i] : 0;
    s[t] = v;
    __syncthreads();
    #pragma unroll
    for (int d = 1; d < 256; d <<= 1) {
        int add = (t >= d) ? s[t - d] : 0;
        __syncthreads();
        s[t] += add;
        __syncthreads();
    }
    if (i < NBINS) g_off[i] = s[t] - v;
    if (t == 255) g_bsum[blockIdx.x] = s[255];
}

__global__ void scan_b_kernel() {
    __shared__ int s[256];
    int t = threadIdx.x;
    int v = (t < SCAN_BLOCKS) ? g_bsum[t] : 0;
    s[t] = v;
    __syncthreads();
    #pragma unroll
    for (int d = 1; d < 256; d <<= 1) {
        int add = (t >= d) ? s[t - d] : 0;
        __syncthreads();
        s[t] += add;
        __syncthreads();
    }
    if (t < SCAN_BLOCKS) g_bsum2[t] = s[t] - v;
}

__global__ void scan_c_kernel() {
    int i = blockIdx.x * blockDim.x + threadIdx.x;
    if (i < NBINS) {
        int off = g_off[i] + g_bsum2[i >> 8];
        g_off[i]    = off;
        g_cursor[i] = off;
    }
    if (i == 0) g_off[NBINS] = N_EDGES;
}

__global__ void reorder_kernel(const int* __restrict__ ei) {
    int e = blockIdx.x * blockDim.x + threadIdx.x;
    if (e >= N_EDGES) return;
    int src = ei[e];
    int dst = ei[N_EDGES + e];
    if ((unsigned)src >= N_NODES || (unsigned)dst >= N_NODES) return;
    int pos = atomicAdd(&g_cursor[dst], 1);
    g_sorted_src[pos] = src;
}

// ---------------------------------------------------------------------------
// Gather-sum + fused bias + PReLU. One warp per dst node. (unchanged)
// ---------------------------------------------------------------------------
__global__ __launch_bounds__(256)
void gather_kernel(const float* __restrict__ bias,
                   const float* __restrict__ prelu_a,
                   float* __restrict__ out) {
    int warp = (blockIdx.x * blockDim.x + threadIdx.x) >> 5;
    int lane = threadIdx.x & 31;
    if (warp >= N_NODES) return;

    int beg = g_off[warp];
    int end = g_off[warp + 1];
    int slot = lane >> 4;
    int cg   = lane & 15;

    float4 acc = make_float4(0.f, 0.f, 0.f, 0.f);
    for (int i = beg + slot; i < end; i += 2) {
        int src = g_sorted_src[i];
        float4 v = *(const float4*)(g_xw + (size_t)src * HID_CH + cg * 4);
        acc.x += v.x; acc.y += v.y; acc.z += v.z; acc.w += v.w;
    }

    acc.x += __shfl_xor_sync(0xFFFFFFFFu, acc.x, 16);
    acc.y += __shfl_xor_sync(0xFFFFFFFFu, acc.y, 16);
    acc.z += __shfl_xor_sync(0xFFFFFFFFu, acc.z, 16);
    acc.w += __shfl_xor_sync(0xFFFFFFFFu, acc.w, 16);

    if (slot == 0) {
        float4 b = ((const float4*)bias)[cg];
        float4 a = ((const float4*)prelu_a)[cg];
        float4 r;
        r.x = acc.x + b.x; r.x = r.x > 0.f ? r.x : a.x * r.x;
        r.y = acc.y + b.y; r.y = r.y > 0.f ? r.y : a.y * r.y;
        r.z = acc.z + b.z; r.z = r.z > 0.f ? r.z : a.z * r.z;
        r.w = acc.w + b.w; r.w = r.w > 0.f ? r.w : a.w * r.w;
        ((float4*)(out + (size_t)warp * HID_CH))[cg] = r;
    }
}

// ---------------------------------------------------------------------------
extern "C" void kernel_launch(void* const* d_in, const int* in_sizes, int n_in,
                              void* d_out, int out_size) {
    const float* x     = (const float*)d_in[0];
    const int*   ei    = (const int*)d_in[1];
    const float* W     = (const float*)d_in[2];
    const float* bias  = (const float*)d_in[3];
    const float* prelu = (const float*)d_in[4];
    float*       out   = (float*)d_out;

    cudaFuncSetAttribute(gemm_mma_kernel, cudaFuncAttributeMaxDynamicSharedMemorySize,
                         GEMM_SMEM_BYTES);

    convert_w_kernel<<<(IN_CH * HID_CH + 255) / 256, 256>>>(W);

    int gemm_blocks = (N_NODES + 127) / 128;   // 391
    gemm_mma_kernel<<<gemm_blocks, 256, GEMM_SMEM_BYTES>>>(x);

    zero_kernel<<<(NBINS + 255) / 256, 256>>>();
    hist_kernel<<<(N_EDGES + 255) / 256, 256>>>(ei);
    scan_a_kernel<<<SCAN_BLOCKS, 256>>>();
    scan_b_kernel<<<1, 256>>>();
    scan_c_kernel<<<SCAN_BLOCKS, 256>>>();
    reorder_kernel<<<(N_EDGES + 255) / 256, 256>>>(ei);

    int gather_blocks = (N_NODES * 32 + 255) / 256;
    gather_kernel<<<gather_blocks, 256>>>(bias, prelu, out);
}